// round 4
// baseline (speedup 1.0000x reference)
#include <cuda_runtime.h>
#include <math.h>

// Problem shape (fixed by the dataset)
#define B_ 8
#define T_ 2048
#define V_ 10
#define H_ 5
#define NC 32     // candidate table capacity per (h,t)
#define NF 8      // fast-path fixed trip count (typical cnt ~ 5-9)
#define PAIRS 64  // (b,t) pairs per block in the fused main kernel

// Scratch (no allocations allowed -> __device__ globals)
__device__ int g_candT[H_ * NC * T_];  // transposed: [(h*NC+slot)*T + t]
__device__ int g_cnt  [H_ * T_];

// ---------------------------------------------------------------------------
// Prep: one warp per (h,t) — pure-fp32 lattice candidate search.
// Exactness: off is a small exact integer so a = t - off is an exact fp32
// integer. 2pi = P1 + P2 with P1 = 6.28125 (9 bits): k*P1 and (a - k*P1 - s)
// are exact; residual d carries ~1e-8 error, far inside the ~6e-5 tie margin.
// Candidates written TRANSPOSED for coalesced reads in the main kernel.
// ---------------------------------------------------------------------------
#define CAND_BLOCKS ((H_ * T_) / 8)   // 8 warps per 256-thread block = 1280

__global__ void k_prep(const float* __restrict__ offs,
                       const float* __restrict__ p_eps,
                       const float* __restrict__ p_C)
{
    int w    = (blockIdx.x * blockDim.x + threadIdx.x) >> 5;
    int lane = threadIdx.x & 31;
    int h = w / T_;
    int t = w - h * T_;

    const float P1     = 6.28125f;                 // 2pi hi (exact, 9 bits)
    const float P2     = 1.9353071795864769e-3f;   // 2pi lo
    const float INV2PI = 0.15915494309189535f;

    float off  = offs[h];
    float quad = 0.5f * p_eps[0];
    float C    = p_C[0];
    float m = 3.0f * (quad * 81.0f / C) + 1e-6f;   // tie margin

    float a = (float)t - off;                      // exact integer
    int kmin = (int)floorf((a - 2047.5f) * INV2PI) - 1;
    int kmax = (int)ceilf ((a + 0.5f)    * INV2PI) + 1;

    // pass 1: min d^2 over valid s in [0, 2047]
    float best = 1e30f;
    for (int k = kmin + lane; k <= kmax; k += 32) {
        float kf = (float)k;
        float r  = __fmaf_rn(-kf, P1, a);          // exact
        float rf = __fmaf_rn(-kf, P2, r);
        float s  = rintf(rf);
        if (s >= 0.0f && s <= 2047.0f) {
            float d = __fmaf_rn(-kf, P2, r - s);   // (r-s) exact
            best = fminf(best, d * d);
        }
    }
#pragma unroll
    for (int o = 16; o; o >>= 1)
        best = fminf(best, __shfl_xor_sync(0xffffffffu, best, o));
    float W2 = best + 2.0f * m + 1e-7f;            // d^2 window

    // pass 2: ordered compaction (k ascending -> s descending), transposed
    int base = 0;
    for (int k0 = kmin; k0 <= kmax; k0 += 32) {
        int k = k0 + lane;
        bool qual = false; int sv = 0;
        if (k <= kmax) {
            float kf = (float)k;
            float r  = __fmaf_rn(-kf, P1, a);
            float rf = __fmaf_rn(-kf, P2, r);
            float s  = rintf(rf);
            if (s >= 0.0f && s <= 2047.0f) {
                float d = __fmaf_rn(-kf, P2, r - s);
                if (d * d <= W2) { qual = true; sv = (int)s; }
            }
        }
        unsigned mask = __ballot_sync(0xffffffffu, qual);
        if (qual) {
            int pos = base + __popc(mask & ((1u << lane) - 1u));
            if (pos < NC) g_candT[(h * NC + pos) * T_ + t] = sv;
        }
        base += __popc(mask);
    }
    if (lane == 0) g_cnt[h * T_ + t] = base;
}

// Faithful fp32 score of candidate s against the rotated query (qr0,qr1).
// Bitwise-identical op sequence to the reference / round-1 passing kernel.
__device__ __forceinline__ float cand_score(int s, int t, float di,
                                            float qr0, float qr1,
                                            float C, float quad, float qk)
{
    const float SQ2 = 1.41421356237309514547f;     // fl32(sqrt(2))
    float ds  = di;
    float x0s = __fsub_rn(C, __fmul_rn(quad, __fmul_rn(ds, ds)));
    float kp  = __fmul_rn(x0s, qk);
    float sf  = (float)s;
    float cs  = cosf(sf), ss = sinf(sf);
    float kr0 = __fmul_rn(kp, cs);                 // k1 component is exactly 0
    float kr1 = __fmul_rn(kp, ss);
    float num = __fmaf_rn(qr1, kr1, __fmul_rn(qr0, kr0));
    float sc  = __fdiv_rn(num, SQ2);
    if (s > t) sc = __fadd_rn(sc, -10000.0f);      // "mask"
    return sc;
}

// ---------------------------------------------------------------------------
// Fused main kernel: one thread per (b,t,h). Block = PAIRS pairs x H_ heads.
// Fast path: fixed NF-trip fully-unrolled candidate loop (loads batched,
// K rows recomputed inline — no dependent table chain). Per-head results
// meet in shared memory; first PAIRS threads run the epilogue.
// ---------------------------------------------------------------------------
__global__ __launch_bounds__(H_ * PAIRS)
void k_fused(const int*   __restrict__ ids,
             const float* __restrict__ o_w,
             const float* __restrict__ w1_abc,
             const float* __restrict__ w2_s,
             const float* __restrict__ p_C,
             const float* __restrict__ p_eps,
             const float* __restrict__ p_qk,
             const float* __restrict__ offs,
             float*       __restrict__ out)
{
    __shared__ float A_s[H_][PAIRS];

    int tid  = threadIdx.x;
    int lane = tid & (PAIRS - 1);
    int h    = tid / PAIRS;
    int p    = blockIdx.x * PAIRS + lane;     // global (b,t) pair
    int b    = p / T_;
    int t    = p - b * T_;
    const int* idb = ids + b * T_;

    const float C    = p_C[0];
    const float eps  = p_eps[0];
    const float qk   = p_qk[0];
    const float quad = __fdiv_rn(eps, 2.0f);

    float dt  = (float)idb[t];
    float x0t = __fsub_rn(C, __fmul_rn(quad, __fmul_rn(dt, dt)));

    // ---- per-(b,t,h) attention via candidate argmax ----
    {
        float tf = (float)t;
        float ct = cosf(tf);
        float st = sinf(tf);
        float off = offs[h];
        float co = cosf(off), so = sinf(off);
        float qb0 = __fmul_rn(co, qk);
        float qb1 = __fmul_rn(-so, qk);
        float q0  = __fmul_rn(x0t, qb0);
        float q1  = __fmul_rn(x0t, qb1);
        float qr0 = __fsub_rn(__fmul_rn(q0, ct), __fmul_rn(q1, st));
        float qr1 = __fadd_rn(__fmul_rn(q0, st), __fmul_rn(q1, ct));

        int cnt = g_cnt[h * T_ + t];
        float A;

        if (cnt <= NF) {
            // --- fast path: fixed trip count, fully unrolled, batched loads ---
            int   sarr[NF];
            float darr[NF];
#pragma unroll
            for (int j = 0; j < NF; ++j)
                sarr[j] = (j < cnt) ? g_candT[(h * NC + j) * T_ + t] : -1;
#pragma unroll
            for (int j = 0; j < NF; ++j)
                darr[j] = (sarr[j] >= 0) ? (float)idb[sarr[j]] : 0.0f;

            float scv[NF];
#pragma unroll
            for (int j = 0; j < NF; ++j)
                scv[j] = (sarr[j] >= 0)
                       ? cand_score(sarr[j], t, darr[j], qr0, qr1, C, quad, qk)
                       : -3.402823466e38f;

            float mx = scv[0];
#pragma unroll
            for (int j = 1; j < NF; ++j) mx = fmaxf(mx, scv[j]);
            int n = 0;
#pragma unroll
            for (int j = 0; j < NF; ++j) if (scv[j] == mx) n++;
            float wgt = __fdiv_rn(1.0f, (float)n);
            float acc = 0.0f;
#pragma unroll
            for (int j = 0; j < NF; ++j)
                if (scv[j] == mx) acc = __fmaf_rn(wgt, darr[j], acc);
            A = acc;
        } else if (cnt <= NC) {
            // --- cold path: variable loop over up to NC slots ---
            float scv[NC];
            float dsv[NC];
            float mx = -3.402823466e38f;
            for (int i = 0; i < cnt; ++i) {
                int   s  = g_candT[(h * NC + i) * T_ + t];
                float di = (float)idb[s];
                float sc = cand_score(s, t, di, qr0, qr1, C, quad, qk);
                scv[i] = sc; dsv[i] = di;
                mx = fmaxf(mx, sc);
            }
            int n = 0;
            for (int i = 0; i < cnt; ++i) if (scv[i] == mx) n++;
            float wgt = __fdiv_rn(1.0f, (float)n);
            float acc = 0.0f;
            for (int i = 0; i < cnt; ++i)
                if (scv[i] == mx) acc = __fmaf_rn(wgt, dsv[i], acc);
            A = acc;
        } else {
            // --- bulletproof fallback: full scan ---
            float mx = -3.402823466e38f;
            int n = 0; float sumd = 0.0f;
            for (int s = 0; s < T_; ++s) {
                float di = (float)idb[s];
                float sc = cand_score(s, t, di, qr0, qr1, C, quad, qk);
                if (sc > mx) { mx = sc; n = 1; sumd = di; }
                else if (sc == mx) { n++; sumd += di; }
            }
            A = __fmul_rn(__fdiv_rn(1.0f, (float)n), sumd);
        }
        A_s[h][lane] = A;
    }
    __syncthreads();

    // ---- epilogue: first PAIRS threads, faithful fp32 ----
    if (tid < PAIRS) {
        float A0 = A_s[0][tid], A1 = A_s[1][tid], A2 = A_s[2][tid],
              A3 = A_s[3][tid], A4 = A_s[4][tid];

        float u0 = __fadd_rn(__fadd_rn(__fmul_rn(o_w[0], A0),
                                       __fmul_rn(o_w[1], A1)),
                             __fmul_rn(o_w[2], A2));
        float u1 = __fadd_rn(__fadd_rn(__fmul_rn(o_w[3], A0),
                                       __fmul_rn(o_w[4], A3)),
                             __fmul_rn(o_w[5], A4));
        float X0 = __fadd_rn(x0t, u0);
        float X1 = __fadd_rn(dt,  u1);

        float wa = w1_abc[0], wb = w1_abc[1], wc = w1_abc[2];
        float b10 = __fsub_rn(C, 8.0f);
        float b11 = __fsub_rn(C, 9.0f);
        float twoC = __fmul_rn(2.0f, C);
        float b12 = __fsub_rn(twoC, 188.0f);
        float b13 = __fsub_rn(twoC, 189.0f);

        float p01 = __fmaf_rn(X1, 0.0f, __fmul_rn(X0, wa));  // rows 0,1: [a,0]
        float p23 = __fmaf_rn(X1, wc,   __fmul_rn(X0, wb));  // rows 2,3: [b,c]
        float h0 = fmaxf(__fadd_rn(p01, b10), 0.0f);
        float h1 = fmaxf(__fadd_rn(p01, b11), 0.0f);
        float h2 = fmaxf(__fadd_rn(p23, b12), 0.0f);
        float h3 = fmaxf(__fadd_rn(p23, b13), 0.0f);

        float s1 = w2_s[0], s10 = w2_s[1];
        float hw = __fmul_rn(h0, s1);
        hw = __fmaf_rn(h1, -s1,  hw);
        hw = __fmaf_rn(h2, -s10, hw);
        hw = __fmaf_rn(h3,  s10, hw);
        float X1b = __fadd_rn(X1, hw);
        float X0b = __fadd_rn(X0, 0.0f);

        float os0 = __fdiv_rn(1.0f, C);
        float y0 = __fmul_rn(X0b, os0);
        float y1 = __fmul_rn(X1b, eps);

        float* o = out + (size_t)p * V_;
#pragma unroll
        for (int j = 0; j < V_; ++j) {
            float jj = (float)(j * j);
            float e0 = __fsub_rn(C, __fmul_rn(quad, jj));
            o[j] = __fmaf_rn(y1, (float)j, __fmul_rn(y0, e0));
        }
    }
}

// ---------------------------------------------------------------------------
// Inputs (metadata order): input_ids(int32), o_w(6), w1_abc(3), w2_s(2),
// embed_const(1), decode_eps(1), qk_scale(1), rope_offsets(5). Output: f32 BxTxV.
// ---------------------------------------------------------------------------
extern "C" void kernel_launch(void* const* d_in, const int* in_sizes, int n_in,
                              void* d_out, int out_size)
{
    const int*   ids    = (const int*)  d_in[0];
    const float* o_w    = (const float*)d_in[1];
    const float* w1_abc = (const float*)d_in[2];
    const float* w2_s   = (const float*)d_in[3];
    const float* p_C    = (const float*)d_in[4];
    const float* p_eps  = (const float*)d_in[5];
    const float* p_qk   = (const float*)d_in[6];
    const float* offs   = (const float*)d_in[7];
    float* out = (float*)d_out;

    k_prep<<<CAND_BLOCKS, 256>>>(offs, p_eps, p_C);

    k_fused<<<(B_ * T_) / PAIRS, H_ * PAIRS>>>(ids, o_w, w1_abc, w2_s,
                                               p_C, p_eps, p_qk, offs, out);
}